// round 6
// baseline (speedup 1.0000x reference)
#include <cuda_runtime.h>
#include <math.h>

#define G_GRAPHS 256
#define K_ATOMS  16
#define N_NODES  4096
#define E_EDGES  61440
#define DEG      15
#define L_LAYERS 3
#define H_HEADS  3
#define F_DIM    64
#define EMB_DIM  200
#define HID_DIM  256

// Scratch buffers (device globals; no allocation allowed)
__device__ float g_fea [N_NODES * F_DIM];
__device__ float g_AB  [(size_t)12 * N_NODES * HID_DIM];   // [h][net][half][n][256]
__device__ float g_hid [(size_t)N_NODES * HID_DIM];
__device__ float g_gate[(size_t)H_HEADS * E_EDGES];
__device__ float g_msg [(size_t)H_HEADS * E_EDGES * F_DIM];

#define ZOFF(h, net, half) ((size_t)((((h)*2 + (net))*2 + (half))) * N_NODES * HID_DIM)

__device__ __forceinline__ float selu_f(float x) {
    const float scale = 1.0507009873554804934193349852946f;
    const float alpha = 1.6732632423543772848170429916717f;
    return x > 0.f ? scale * x : scale * alpha * (__expf(x) - 1.f);
}

// ---- packed fp32x2 helpers (sm_100+ PTX; ptxas never emits FFMA2 from C++) --
__device__ __forceinline__ unsigned long long bcast2(float x) {
    unsigned long long r;
    asm("mov.b64 %0, {%1, %1};" : "=l"(r) : "f"(x));
    return r;
}
__device__ __forceinline__ void fma2(unsigned long long& d,
                                     unsigned long long a, unsigned long long b) {
    asm("fma.rn.f32x2 %0, %1, %2, %0;" : "+l"(d) : "l"(a), "l"(b));
}
__device__ __forceinline__ float2 unpack2(unsigned long long v) {
    float lo, hi;
    asm("mov.b64 {%0, %1}, %2;" : "=f"(lo), "=f"(hi) : "l"(v));
    return make_float2(lo, hi);
}

// ---------------------------------------------------------------------------
// Batched node projection GEMM for one layer:
// AB[z] = fea[4096,64] @ W_z[64,256]   for z in 0..11  (h, net, half)
// ---------------------------------------------------------------------------
__global__ __launch_bounds__(256) void node_gemm(
    const float* __restrict__ fea, const float* __restrict__ mgW1,
    const float* __restrict__ mmW1, float* __restrict__ AB, int l)
{
    const int z    = blockIdx.z;
    const int h    = z >> 2;
    const int net  = (z >> 1) & 1;
    const int half = z & 1;
    const int lh   = l * H_HEADS + h;
    const float* W = (net ? mmW1 : mgW1) + ((size_t)lh * 128 + half * 64) * HID_DIM;
    float* Y = AB + (size_t)z * N_NODES * HID_DIM;

    __shared__ float As[64][17];
    __shared__ __align__(16) float Bs[16][64];
    const int tid  = threadIdx.x;
    const int row0 = blockIdx.y * 64;
    const int col0 = blockIdx.x * 64;
    const int tr = tid >> 4, tc = tid & 15;

    unsigned long long acc2[4][2];
#pragma unroll
    for (int i = 0; i < 4; i++) { acc2[i][0] = 0ull; acc2[i][1] = 0ull; }

    const int ar = tid >> 2, ac = (tid & 3) << 2;
    const int br = tid >> 4, bc = (tid & 15) << 2;

#pragma unroll
    for (int k0 = 0; k0 < 64; k0 += 16) {
        float4 av = *reinterpret_cast<const float4*>(fea + (size_t)(row0 + ar) * 64 + k0 + ac);
        As[ar][ac + 0] = av.x; As[ar][ac + 1] = av.y;
        As[ar][ac + 2] = av.z; As[ar][ac + 3] = av.w;
        float4 bv = *reinterpret_cast<const float4*>(W + (size_t)(k0 + br) * HID_DIM + col0 + bc);
        *reinterpret_cast<float4*>(&Bs[br][bc]) = bv;
        __syncthreads();
#pragma unroll
        for (int k = 0; k < 16; k++) {
            const unsigned long long* bp =
                reinterpret_cast<const unsigned long long*>(&Bs[k][tc * 4]);
            unsigned long long b01 = bp[0], b23 = bp[1];
            unsigned long long A0 = bcast2(As[tr * 4 + 0][k]);
            unsigned long long A1 = bcast2(As[tr * 4 + 1][k]);
            unsigned long long A2 = bcast2(As[tr * 4 + 2][k]);
            unsigned long long A3 = bcast2(As[tr * 4 + 3][k]);
            fma2(acc2[0][0], A0, b01); fma2(acc2[0][1], A0, b23);
            fma2(acc2[1][0], A1, b01); fma2(acc2[1][1], A1, b23);
            fma2(acc2[2][0], A2, b01); fma2(acc2[2][1], A2, b23);
            fma2(acc2[3][0], A3, b01); fma2(acc2[3][1], A3, b23);
        }
        __syncthreads();
    }
#pragma unroll
    for (int i = 0; i < 4; i++) {
        int r = row0 + tr * 4 + i;
        float2 v01 = unpack2(acc2[i][0]);
        float2 v23 = unpack2(acc2[i][1]);
        float4 v = make_float4(v01.x, v01.y, v23.x, v23.y);
        *reinterpret_cast<float4*>(Y + (size_t)r * HID_DIM + col0 + tc * 4) = v;
    }
}

// ---------------------------------------------------------------------------
// Fused per-edge gate + message kernel (one head per blockIdx.z):
//   gate[h][e] = selu(Ag[s]+Bg[n]+b1g) . w2g + b2g       (register-reduced)
//   msg [h][e] = selu(Am[s]+Bm[n]+b1m) @ W2[256,64] + b2 (smem-tiled GEMM)
// Tile: 128 edges x 64 outputs, K-tile 16.  Packed f32x2 MMA (row-paired).
// ---------------------------------------------------------------------------
__global__ __launch_bounds__(256) void msg_gate_gemm(
    const float* __restrict__ AB,
    const float* __restrict__ mg_b1, const float* __restrict__ mg_W2,
    const float* __restrict__ mg_b2,
    const float* __restrict__ mm_b1, const float* __restrict__ mm_W2,
    const float* __restrict__ mm_b2,
    const int* __restrict__ nbr_idx,
    float* __restrict__ gate, float* __restrict__ msg, int l)
{
    const int h  = blockIdx.z;
    const int lh = l * H_HEADS + h;
    const int e0 = blockIdx.x * 128;
    const int tid = threadIdx.x;

    __shared__ int   sI[128], nI[128];
    __shared__ float b1m[HID_DIM], b1g[HID_DIM], w2g[HID_DIM];
    __shared__ __align__(16) float As[16][136];
    __shared__ __align__(16) float Bs[16][68];

    if (tid < 128) {
        int e = e0 + tid;
        sI[tid] = e / DEG;
        nI[tid] = nbr_idx[e];
    }
    {   // tid 0..255 covers all 256
        b1m[tid] = mm_b1[(size_t)lh * HID_DIM + tid];
        b1g[tid] = mg_b1[(size_t)lh * HID_DIM + tid];
        w2g[tid] = mg_W2[(size_t)lh * HID_DIM + tid];
    }

    const float* Am = AB + ZOFF(h, 1, 0);
    const float* Bm = AB + ZOFF(h, 1, 1);
    const float* Ag = AB + ZOFF(h, 0, 0);
    const float* Bg = AB + ZOFF(h, 0, 1);
    const float* W2 = mm_W2 + (size_t)lh * HID_DIM * F_DIM;
    __syncthreads();

    const int tr = tid >> 4, tc = tid & 15;   // 16x16 thread grid for MMA
    const int gr = tid >> 1;                  // generation edge row (0..127)
    const int gk = (tid & 1) * 8;             // generation k-offset (0 or 8)
    const int wr = tid >> 4;                  // Bs load row
    const int wc = (tid & 15) * 4;            // Bs load col

    const int sRow = sI[gr], nRow = nI[gr];
    const float* amp = Am + (size_t)sRow * HID_DIM + gk;
    const float* bmp = Bm + (size_t)nRow * HID_DIM + gk;
    const float* agp = Ag + (size_t)sRow * HID_DIM + gk;
    const float* bgp = Bg + (size_t)nRow * HID_DIM + gk;

    // acc2[rp][j]: packed pair of edge rows (tr*8+2rp, tr*8+2rp+1), column tc*4+j
    unsigned long long acc2[4][4];
#pragma unroll
    for (int i = 0; i < 4; i++)
#pragma unroll
        for (int j = 0; j < 4; j++) acc2[i][j] = 0ull;
    float gacc = 0.f;

    for (int k0 = 0; k0 < HID_DIM; k0 += 16) {
        // --- generate msg activation tile As[k][edge] ---
        {
            float4 a0 = *reinterpret_cast<const float4*>(amp + k0);
            float4 a1 = *reinterpret_cast<const float4*>(amp + k0 + 4);
            float4 c0 = *reinterpret_cast<const float4*>(bmp + k0);
            float4 c1 = *reinterpret_cast<const float4*>(bmp + k0 + 4);
            const float* bb = b1m + k0 + gk;
            As[gk + 0][gr] = selu_f(a0.x + c0.x + bb[0]);
            As[gk + 1][gr] = selu_f(a0.y + c0.y + bb[1]);
            As[gk + 2][gr] = selu_f(a0.z + c0.z + bb[2]);
            As[gk + 3][gr] = selu_f(a0.w + c0.w + bb[3]);
            As[gk + 4][gr] = selu_f(a1.x + c1.x + bb[4]);
            As[gk + 5][gr] = selu_f(a1.y + c1.y + bb[5]);
            As[gk + 6][gr] = selu_f(a1.z + c1.z + bb[6]);
            As[gk + 7][gr] = selu_f(a1.w + c1.w + bb[7]);
        }
        // --- gate partial (register accumulation, no smem) ---
        {
            float4 a0 = *reinterpret_cast<const float4*>(agp + k0);
            float4 a1 = *reinterpret_cast<const float4*>(agp + k0 + 4);
            float4 c0 = *reinterpret_cast<const float4*>(bgp + k0);
            float4 c1 = *reinterpret_cast<const float4*>(bgp + k0 + 4);
            const float* bb = b1g + k0 + gk;
            const float* ww = w2g + k0 + gk;
            gacc += selu_f(a0.x + c0.x + bb[0]) * ww[0];
            gacc += selu_f(a0.y + c0.y + bb[1]) * ww[1];
            gacc += selu_f(a0.z + c0.z + bb[2]) * ww[2];
            gacc += selu_f(a0.w + c0.w + bb[3]) * ww[3];
            gacc += selu_f(a1.x + c1.x + bb[4]) * ww[4];
            gacc += selu_f(a1.y + c1.y + bb[5]) * ww[5];
            gacc += selu_f(a1.z + c1.z + bb[6]) * ww[6];
            gacc += selu_f(a1.w + c1.w + bb[7]) * ww[7];
        }
        // --- W2 tile ---
        *reinterpret_cast<float4*>(&Bs[wr][wc]) =
            *reinterpret_cast<const float4*>(W2 + (size_t)(k0 + wr) * F_DIM + wc);
        __syncthreads();
#pragma unroll
        for (int k = 0; k < 16; k++) {
            // a: 8 consecutive edges as 4 packed u64 lanes (straight from LDS.128)
            const ulonglong2* ap = reinterpret_cast<const ulonglong2*>(&As[k][tr * 8]);
            ulonglong2 aA = ap[0];   // edges (0,1),(2,3)
            ulonglong2 aB = ap[1];   // edges (4,5),(6,7)
            float4 b = *reinterpret_cast<const float4*>(&Bs[k][tc * 4]);
            unsigned long long B0 = bcast2(b.x), B1 = bcast2(b.y);
            unsigned long long B2 = bcast2(b.z), B3 = bcast2(b.w);
            fma2(acc2[0][0], aA.x, B0); fma2(acc2[0][1], aA.x, B1);
            fma2(acc2[0][2], aA.x, B2); fma2(acc2[0][3], aA.x, B3);
            fma2(acc2[1][0], aA.y, B0); fma2(acc2[1][1], aA.y, B1);
            fma2(acc2[1][2], aA.y, B2); fma2(acc2[1][3], aA.y, B3);
            fma2(acc2[2][0], aB.x, B0); fma2(acc2[2][1], aB.x, B1);
            fma2(acc2[2][2], aB.x, B2); fma2(acc2[2][3], aB.x, B3);
            fma2(acc2[3][0], aB.y, B0); fma2(acc2[3][1], aB.y, B1);
            fma2(acc2[3][2], aB.y, B2); fma2(acc2[3][3], aB.y, B3);
        }
        __syncthreads();
    }

    // gate: combine the two k-halves (adjacent threads) and write
    gacc += __shfl_xor_sync(0xffffffffu, gacc, 1);
    if ((tid & 1) == 0)
        gate[(size_t)h * E_EDGES + e0 + gr] = gacc + mg_b2[lh];

    // msg output: unpack row pairs
    const float* b2 = mm_b2 + (size_t)lh * F_DIM;
    float4 bias;
    bias.x = b2[tc * 4 + 0]; bias.y = b2[tc * 4 + 1];
    bias.z = b2[tc * 4 + 2]; bias.w = b2[tc * 4 + 3];
#pragma unroll
    for (int rp = 0; rp < 4; rp++) {
        float2 c0 = unpack2(acc2[rp][0]);
        float2 c1 = unpack2(acc2[rp][1]);
        float2 c2 = unpack2(acc2[rp][2]);
        float2 c3 = unpack2(acc2[rp][3]);
        int eLo = e0 + tr * 8 + rp * 2;
        float4 vLo = make_float4(c0.x + bias.x, c1.x + bias.y, c2.x + bias.z, c3.x + bias.w);
        float4 vHi = make_float4(c0.y + bias.x, c1.y + bias.y, c2.y + bias.z, c3.y + bias.w);
        *reinterpret_cast<float4*>(msg + ((size_t)h * E_EDGES + eLo) * F_DIM + tc * 4) = vLo;
        *reinterpret_cast<float4*>(msg + ((size_t)h * E_EDGES + eLo + 1) * F_DIM + tc * 4) = vHi;
    }
}

// ---------------------------------------------------------------------------
// Generic GEMM Y = act(X @ W + b)  (pooling path), packed f32x2
// ---------------------------------------------------------------------------
__global__ __launch_bounds__(256) void gemm_bias_act(
    const float* __restrict__ X, const float* __restrict__ W,
    const float* __restrict__ bias, float* __restrict__ Y,
    int M, int Kd, int N, int doSelu)
{
    __shared__ float As[64][17];
    __shared__ __align__(16) float Bs[16][64];
    const int tid  = threadIdx.x;
    const int row0 = blockIdx.y * 64;
    const int col0 = blockIdx.x * 64;
    const int tr = tid >> 4, tc = tid & 15;

    unsigned long long acc2[4][2];
#pragma unroll
    for (int i = 0; i < 4; i++) { acc2[i][0] = 0ull; acc2[i][1] = 0ull; }

    const int ar = tid >> 2, ac = (tid & 3) << 2;
    const int br = tid >> 4, bc = (tid & 15) << 2;

    for (int k0 = 0; k0 < Kd; k0 += 16) {
        float4 av = *reinterpret_cast<const float4*>(X + (size_t)(row0 + ar) * Kd + k0 + ac);
        As[ar][ac + 0] = av.x; As[ar][ac + 1] = av.y;
        As[ar][ac + 2] = av.z; As[ar][ac + 3] = av.w;
        float4 bv = *reinterpret_cast<const float4*>(W + (size_t)(k0 + br) * N + col0 + bc);
        *reinterpret_cast<float4*>(&Bs[br][bc]) = bv;
        __syncthreads();
#pragma unroll
        for (int k = 0; k < 16; k++) {
            const unsigned long long* bp =
                reinterpret_cast<const unsigned long long*>(&Bs[k][tc * 4]);
            unsigned long long b01 = bp[0], b23 = bp[1];
            unsigned long long A0 = bcast2(As[tr * 4 + 0][k]);
            unsigned long long A1 = bcast2(As[tr * 4 + 1][k]);
            unsigned long long A2 = bcast2(As[tr * 4 + 2][k]);
            unsigned long long A3 = bcast2(As[tr * 4 + 3][k]);
            fma2(acc2[0][0], A0, b01); fma2(acc2[0][1], A0, b23);
            fma2(acc2[1][0], A1, b01); fma2(acc2[1][1], A1, b23);
            fma2(acc2[2][0], A2, b01); fma2(acc2[2][1], A2, b23);
            fma2(acc2[3][0], A3, b01); fma2(acc2[3][1], A3, b23);
        }
        __syncthreads();
    }
#pragma unroll
    for (int i = 0; i < 4; i++) {
        int r = row0 + tr * 4 + i;
        float2 v01 = unpack2(acc2[i][0]);
        float2 v23 = unpack2(acc2[i][1]);
        float vv[4] = {v01.x, v01.y, v23.x, v23.y};
#pragma unroll
        for (int j = 0; j < 4; j++) {
            int c = col0 + tc * 4 + j;
            float v = vv[j] + bias[c];
            if (doSelu) v = selu_f(v);
            Y[(size_t)r * N + c] = v;
        }
    }
}

__global__ __launch_bounds__(256) void rowdot256(
    const float* __restrict__ H, const float* __restrict__ w2,
    const float* __restrict__ b2, float* __restrict__ out)
{
    int row  = blockIdx.x * 8 + (threadIdx.x >> 5);
    int lane = threadIdx.x & 31;
    const float* h = H + (size_t)row * HID_DIM;
    float s = 0.f;
#pragma unroll
    for (int k = lane; k < HID_DIM; k += 32) s += h[k] * w2[k];
#pragma unroll
    for (int o = 16; o; o >>= 1) s += __shfl_xor_sync(0xffffffffu, s, o);
    if (lane == 0) out[row] = s + b2[0];
}

__global__ __launch_bounds__(64) void embed_kernel(
    const float* __restrict__ X, const float* __restrict__ W,
    const float* __restrict__ b, const float* __restrict__ w,
    float* __restrict__ fea)
{
    __shared__ float row[EMB_DIM];
    int n = blockIdx.x, tid = threadIdx.x;
    for (int i = tid; i < EMB_DIM; i += 64) row[i] = X[(size_t)n * EMB_DIM + i];
    __syncthreads();
    if (tid < 63) {
        float s = b[tid];
#pragma unroll 8
        for (int k = 0; k < EMB_DIM; k++) s += row[k] * W[k * 63 + tid];
        fea[n * F_DIM + tid] = s;
    } else {
        fea[n * F_DIM + 63] = w[n];
    }
}

__global__ __launch_bounds__(64) void node_agg(
    const float* __restrict__ gate, const float* __restrict__ msg,
    const float* __restrict__ ew, const int* __restrict__ nbr_idx,
    const float* __restrict__ powp, float* __restrict__ fea)
{
    __shared__ float attn[H_HEADS][DEG];
    int n = blockIdx.x, tid = threadIdx.x;
    if (tid < H_HEADS) {
        int h = tid;
        float pw = powp[h];
        float g[DEG], t[DEG];
        float mx = -1e30f;
#pragma unroll
        for (int e = 0; e < DEG; e++) {
            g[e] = gate[(size_t)h * E_EDGES + n * DEG + e];
            mx = fmaxf(mx, g[e]);
        }
        float den = 0.f;
#pragma unroll
        for (int e = 0; e < DEG; e++) {
            float wv = powf(ew[nbr_idx[n * DEG + e]], pw);
            t[e] = wv * expf(g[e] - mx);
            den += t[e];
        }
        den += 1e-10f;
        float inv = 1.f / den;
#pragma unroll
        for (int e = 0; e < DEG; e++) attn[h][e] = t[e] * inv;
    }
    __syncthreads();
    float acc = 0.f;
#pragma unroll
    for (int h = 0; h < H_HEADS; h++)
#pragma unroll
        for (int e = 0; e < DEG; e++)
            acc += attn[h][e] * msg[((size_t)h * E_EDGES + n * DEG + e) * F_DIM + tid];
    fea[n * F_DIM + tid] += acc * (1.f / 3.f);
}

__global__ __launch_bounds__(64) void graph_agg(
    const float* __restrict__ gate, const float* __restrict__ msg,
    const float* __restrict__ ew, const float* __restrict__ powp,
    float* __restrict__ out)
{
    __shared__ float attn[H_HEADS][K_ATOMS];
    int g = blockIdx.x, tid = threadIdx.x;
    if (tid < H_HEADS) {
        int h = tid;
        float pw = powp[h];
        float gg[K_ATOMS], t[K_ATOMS];
        float mx = -1e30f;
#pragma unroll
        for (int e = 0; e < K_ATOMS; e++) {
            gg[e] = gate[(size_t)h * N_NODES + g * K_ATOMS + e];
            mx = fmaxf(mx, gg[e]);
        }
        float den = 0.f;
#pragma unroll
        for (int e = 0; e < K_ATOMS; e++) {
            float wv = powf(ew[g * K_ATOMS + e], pw);
            t[e] = wv * expf(gg[e] - mx);
            den += t[e];
        }
        den += 1e-10f;
        float inv = 1.f / den;
#pragma unroll
        for (int e = 0; e < K_ATOMS; e++) attn[h][e] = t[e] * inv;
    }
    __syncthreads();
    float acc = 0.f;
#pragma unroll
    for (int h = 0; h < H_HEADS; h++)
#pragma unroll
        for (int e = 0; e < K_ATOMS; e++)
            acc += attn[h][e] * msg[((size_t)h * N_NODES + g * K_ATOMS + e) * F_DIM + tid];
    out[g * F_DIM + tid] = acc * (1.f / 3.f);
}

extern "C" void kernel_launch(void* const* d_in, const int* in_sizes, int n_in,
                              void* d_out, int out_size)
{
    const float* elem_weights = (const float*)d_in[0];
    const float* elem_fea_in  = (const float*)d_in[1];
    const float* W_init       = (const float*)d_in[2];
    const float* b_init       = (const float*)d_in[3];
    const float* mg_W1        = (const float*)d_in[4];
    const float* mg_b1        = (const float*)d_in[5];
    const float* mg_W2        = (const float*)d_in[6];
    const float* mg_b2        = (const float*)d_in[7];
    const float* mm_W1        = (const float*)d_in[8];
    const float* mm_b1        = (const float*)d_in[9];
    const float* mm_W2        = (const float*)d_in[10];
    const float* mm_b2        = (const float*)d_in[11];
    const float* m_pow        = (const float*)d_in[12];
    const float* cg_W1        = (const float*)d_in[13];
    const float* cg_b1        = (const float*)d_in[14];
    const float* cg_W2        = (const float*)d_in[15];
    const float* cg_b2        = (const float*)d_in[16];
    const float* cm_W1        = (const float*)d_in[17];
    const float* cm_b1        = (const float*)d_in[18];
    const float* cm_W2        = (const float*)d_in[19];
    const float* cm_b2        = (const float*)d_in[20];
    const float* c_pow        = (const float*)d_in[21];
    const int*   nbr_idx      = (const int*)d_in[24];

    float *fea, *AB, *hid, *gate, *msg;
    cudaGetSymbolAddress((void**)&fea,  g_fea);
    cudaGetSymbolAddress((void**)&AB,   g_AB);
    cudaGetSymbolAddress((void**)&hid,  g_hid);
    cudaGetSymbolAddress((void**)&gate, g_gate);
    cudaGetSymbolAddress((void**)&msg,  g_msg);

    embed_kernel<<<N_NODES, 64>>>(elem_fea_in, W_init, b_init, elem_weights, fea);

    for (int l = 0; l < L_LAYERS; l++) {
        node_gemm<<<dim3(HID_DIM / 64, N_NODES / 64, 12), 256>>>(fea, mg_W1, mm_W1, AB, l);
        msg_gate_gemm<<<dim3(E_EDGES / 128, 1, H_HEADS), 256>>>(
            AB, mg_b1, mg_W2, mg_b2, mm_b1, mm_W2, mm_b2, nbr_idx, gate, msg, l);
        node_agg<<<N_NODES, 64>>>(gate, msg, elem_weights, nbr_idx,
                                  m_pow + l * H_HEADS, fea);
    }

    for (int h = 0; h < H_HEADS; h++) {
        gemm_bias_act<<<dim3(HID_DIM / 64, N_NODES / 64), 256>>>(
            fea, cg_W1 + (size_t)h * F_DIM * HID_DIM, cg_b1 + (size_t)h * HID_DIM,
            hid, N_NODES, F_DIM, HID_DIM, 1);
        rowdot256<<<N_NODES / 8, 256>>>(hid, cg_W2 + (size_t)h * HID_DIM,
                                        cg_b2 + h, gate + (size_t)h * N_NODES);
        gemm_bias_act<<<dim3(HID_DIM / 64, N_NODES / 64), 256>>>(
            fea, cm_W1 + (size_t)h * F_DIM * HID_DIM, cm_b1 + (size_t)h * HID_DIM,
            hid, N_NODES, F_DIM, HID_DIM, 1);
        gemm_bias_act<<<dim3(F_DIM / 64, N_NODES / 64), 256>>>(
            hid, cm_W2 + (size_t)h * HID_DIM * F_DIM, cm_b2 + (size_t)h * F_DIM,
            msg + (size_t)h * N_NODES * F_DIM, N_NODES, HID_DIM, F_DIM, 0);
    }

    graph_agg<<<G_GRAPHS, 64>>>(gate, msg, elem_weights, c_pow, (float*)d_out);
}

// round 7
// speedup vs baseline: 1.0032x; 1.0032x over previous
#include <cuda_runtime.h>
#include <math.h>

#define G_GRAPHS 256
#define K_ATOMS  16
#define N_NODES  4096
#define E_EDGES  61440
#define DEG      15
#define L_LAYERS 3
#define H_HEADS  3
#define F_DIM    64
#define EMB_DIM  200
#define HID_DIM  256

// Scratch buffers (device globals; no allocation allowed)
__device__ float g_fea [N_NODES * F_DIM];
__device__ float g_AB  [(size_t)12 * N_NODES * HID_DIM];   // [h][net][half][n][256]
__device__ float g_hid [(size_t)N_NODES * HID_DIM];
__device__ float g_gate[(size_t)H_HEADS * E_EDGES];
__device__ float g_msg [(size_t)H_HEADS * E_EDGES * F_DIM];

#define ZOFF(h, net, half) ((size_t)((((h)*2 + (net))*2 + (half))) * N_NODES * HID_DIM)

__device__ __forceinline__ float selu_f(float x) {
    const float scale = 1.0507009873554804934193349852946f;
    const float alpha = 1.6732632423543772848170429916717f;
    return x > 0.f ? scale * x : scale * alpha * (__expf(x) - 1.f);
}

// ---- packed fp32x2 helpers (sm_100+ PTX; ptxas never emits FFMA2 from C++) --
__device__ __forceinline__ unsigned long long bcast2(float x) {
    unsigned long long r;
    asm("mov.b64 %0, {%1, %1};" : "=l"(r) : "f"(x));
    return r;
}
__device__ __forceinline__ void fma2(unsigned long long& d,
                                     unsigned long long a, unsigned long long b) {
    asm("fma.rn.f32x2 %0, %1, %2, %0;" : "+l"(d) : "l"(a), "l"(b));
}
__device__ __forceinline__ float2 unpack2(unsigned long long v) {
    float lo, hi;
    asm("mov.b64 {%0, %1}, %2;" : "=f"(lo), "=f"(hi) : "l"(v));
    return make_float2(lo, hi);
}

// ---------------------------------------------------------------------------
// Batched node projection GEMM for one layer:
// AB[z] = fea[4096,64] @ W_z[64,256]   for z in 0..11  (h, net, half)
// ---------------------------------------------------------------------------
__global__ __launch_bounds__(256) void node_gemm(
    const float* __restrict__ fea, const float* __restrict__ mgW1,
    const float* __restrict__ mmW1, float* __restrict__ AB, int l)
{
    const int z    = blockIdx.z;
    const int h    = z >> 2;
    const int net  = (z >> 1) & 1;
    const int half = z & 1;
    const int lh   = l * H_HEADS + h;
    const float* W = (net ? mmW1 : mgW1) + ((size_t)lh * 128 + half * 64) * HID_DIM;
    float* Y = AB + (size_t)z * N_NODES * HID_DIM;

    __shared__ float As[64][17];
    __shared__ __align__(16) float Bs[16][64];
    const int tid  = threadIdx.x;
    const int row0 = blockIdx.y * 64;
    const int col0 = blockIdx.x * 64;
    const int tr = tid >> 4, tc = tid & 15;

    unsigned long long acc2[4][2];
#pragma unroll
    for (int i = 0; i < 4; i++) { acc2[i][0] = 0ull; acc2[i][1] = 0ull; }

    const int ar = tid >> 2, ac = (tid & 3) << 2;
    const int br = tid >> 4, bc = (tid & 15) << 2;

#pragma unroll
    for (int k0 = 0; k0 < 64; k0 += 16) {
        float4 av = *reinterpret_cast<const float4*>(fea + (size_t)(row0 + ar) * 64 + k0 + ac);
        As[ar][ac + 0] = av.x; As[ar][ac + 1] = av.y;
        As[ar][ac + 2] = av.z; As[ar][ac + 3] = av.w;
        float4 bv = *reinterpret_cast<const float4*>(W + (size_t)(k0 + br) * HID_DIM + col0 + bc);
        *reinterpret_cast<float4*>(&Bs[br][bc]) = bv;
        __syncthreads();
#pragma unroll
        for (int k = 0; k < 16; k++) {
            const unsigned long long* bp =
                reinterpret_cast<const unsigned long long*>(&Bs[k][tc * 4]);
            unsigned long long b01 = bp[0], b23 = bp[1];
            unsigned long long A0 = bcast2(As[tr * 4 + 0][k]);
            unsigned long long A1 = bcast2(As[tr * 4 + 1][k]);
            unsigned long long A2 = bcast2(As[tr * 4 + 2][k]);
            unsigned long long A3 = bcast2(As[tr * 4 + 3][k]);
            fma2(acc2[0][0], A0, b01); fma2(acc2[0][1], A0, b23);
            fma2(acc2[1][0], A1, b01); fma2(acc2[1][1], A1, b23);
            fma2(acc2[2][0], A2, b01); fma2(acc2[2][1], A2, b23);
            fma2(acc2[3][0], A3, b01); fma2(acc2[3][1], A3, b23);
        }
        __syncthreads();
    }
#pragma unroll
    for (int i = 0; i < 4; i++) {
        int r = row0 + tr * 4 + i;
        float2 v01 = unpack2(acc2[i][0]);
        float2 v23 = unpack2(acc2[i][1]);
        float4 v = make_float4(v01.x, v01.y, v23.x, v23.y);
        *reinterpret_cast<float4*>(Y + (size_t)r * HID_DIM + col0 + tc * 4) = v;
    }
}

// ---------------------------------------------------------------------------
// Fused per-edge gate + message kernel (one head per blockIdx.z):
//   gate[h][e] = selu(Ag[s]+Bg[n]+b1g) . w2g + b2g       (register-reduced)
//   msg [h][e] = selu(Am[s]+Bm[n]+b1m) @ W2[256,64] + b2 (smem-tiled GEMM)
// Tile: 128 edges x 64 outputs, K-tile 16.  Packed f32x2 MMA (row-paired).
// ---------------------------------------------------------------------------
__global__ __launch_bounds__(256) void msg_gate_gemm(
    const float* __restrict__ AB,
    const float* __restrict__ mg_b1, const float* __restrict__ mg_W2,
    const float* __restrict__ mg_b2,
    const float* __restrict__ mm_b1, const float* __restrict__ mm_W2,
    const float* __restrict__ mm_b2,
    const int* __restrict__ nbr_idx,
    float* __restrict__ gate, float* __restrict__ msg, int l)
{
    const int h  = blockIdx.z;
    const int lh = l * H_HEADS + h;
    const int e0 = blockIdx.x * 128;
    const int tid = threadIdx.x;

    __shared__ int   sI[128], nI[128];
    __shared__ float b1m[HID_DIM], b1g[HID_DIM], w2g[HID_DIM];
    __shared__ __align__(16) float As[16][136];
    __shared__ __align__(16) float Bs[16][68];

    if (tid < 128) {
        int e = e0 + tid;
        sI[tid] = e / DEG;
        nI[tid] = nbr_idx[e];
    }
    {   // tid 0..255 covers all 256
        b1m[tid] = mm_b1[(size_t)lh * HID_DIM + tid];
        b1g[tid] = mg_b1[(size_t)lh * HID_DIM + tid];
        w2g[tid] = mg_W2[(size_t)lh * HID_DIM + tid];
    }

    const float* Am = AB + ZOFF(h, 1, 0);
    const float* Bm = AB + ZOFF(h, 1, 1);
    const float* Ag = AB + ZOFF(h, 0, 0);
    const float* Bg = AB + ZOFF(h, 0, 1);
    const float* W2 = mm_W2 + (size_t)lh * HID_DIM * F_DIM;
    __syncthreads();

    const int tr = tid >> 4, tc = tid & 15;   // 16x16 thread grid for MMA
    const int gr = tid >> 1;                  // generation edge row (0..127)
    const int gk = (tid & 1) * 8;             // generation k-offset (0 or 8)
    const int wr = tid >> 4;                  // Bs load row
    const int wc = (tid & 15) * 4;            // Bs load col

    const int sRow = sI[gr], nRow = nI[gr];
    const float* amp = Am + (size_t)sRow * HID_DIM + gk;
    const float* bmp = Bm + (size_t)nRow * HID_DIM + gk;
    const float* agp = Ag + (size_t)sRow * HID_DIM + gk;
    const float* bgp = Bg + (size_t)nRow * HID_DIM + gk;

    // acc2[rp][j]: packed pair of edge rows (tr*8+2rp, tr*8+2rp+1), column tc*4+j
    unsigned long long acc2[4][4];
#pragma unroll
    for (int i = 0; i < 4; i++)
#pragma unroll
        for (int j = 0; j < 4; j++) acc2[i][j] = 0ull;
    float gacc = 0.f;

    for (int k0 = 0; k0 < HID_DIM; k0 += 16) {
        // --- generate msg activation tile As[k][edge] ---
        {
            float4 a0 = *reinterpret_cast<const float4*>(amp + k0);
            float4 a1 = *reinterpret_cast<const float4*>(amp + k0 + 4);
            float4 c0 = *reinterpret_cast<const float4*>(bmp + k0);
            float4 c1 = *reinterpret_cast<const float4*>(bmp + k0 + 4);
            const float* bb = b1m + k0 + gk;
            As[gk + 0][gr] = selu_f(a0.x + c0.x + bb[0]);
            As[gk + 1][gr] = selu_f(a0.y + c0.y + bb[1]);
            As[gk + 2][gr] = selu_f(a0.z + c0.z + bb[2]);
            As[gk + 3][gr] = selu_f(a0.w + c0.w + bb[3]);
            As[gk + 4][gr] = selu_f(a1.x + c1.x + bb[4]);
            As[gk + 5][gr] = selu_f(a1.y + c1.y + bb[5]);
            As[gk + 6][gr] = selu_f(a1.z + c1.z + bb[6]);
            As[gk + 7][gr] = selu_f(a1.w + c1.w + bb[7]);
        }
        // --- gate partial (register accumulation, no smem) ---
        {
            float4 a0 = *reinterpret_cast<const float4*>(agp + k0);
            float4 a1 = *reinterpret_cast<const float4*>(agp + k0 + 4);
            float4 c0 = *reinterpret_cast<const float4*>(bgp + k0);
            float4 c1 = *reinterpret_cast<const float4*>(bgp + k0 + 4);
            const float* bb = b1g + k0 + gk;
            const float* ww = w2g + k0 + gk;
            gacc += selu_f(a0.x + c0.x + bb[0]) * ww[0];
            gacc += selu_f(a0.y + c0.y + bb[1]) * ww[1];
            gacc += selu_f(a0.z + c0.z + bb[2]) * ww[2];
            gacc += selu_f(a0.w + c0.w + bb[3]) * ww[3];
            gacc += selu_f(a1.x + c1.x + bb[4]) * ww[4];
            gacc += selu_f(a1.y + c1.y + bb[5]) * ww[5];
            gacc += selu_f(a1.z + c1.z + bb[6]) * ww[6];
            gacc += selu_f(a1.w + c1.w + bb[7]) * ww[7];
        }
        // --- W2 tile ---
        *reinterpret_cast<float4*>(&Bs[wr][wc]) =
            *reinterpret_cast<const float4*>(W2 + (size_t)(k0 + wr) * F_DIM + wc);
        __syncthreads();
#pragma unroll
        for (int k = 0; k < 16; k++) {
            // a: 8 consecutive edges as 4 packed u64 lanes (straight from LDS.128)
            const ulonglong2* ap = reinterpret_cast<const ulonglong2*>(&As[k][tr * 8]);
            ulonglong2 aA = ap[0];   // edges (0,1),(2,3)
            ulonglong2 aB = ap[1];   // edges (4,5),(6,7)
            float4 b = *reinterpret_cast<const float4*>(&Bs[k][tc * 4]);
            unsigned long long B0 = bcast2(b.x), B1 = bcast2(b.y);
            unsigned long long B2 = bcast2(b.z), B3 = bcast2(b.w);
            fma2(acc2[0][0], aA.x, B0); fma2(acc2[0][1], aA.x, B1);
            fma2(acc2[0][2], aA.x, B2); fma2(acc2[0][3], aA.x, B3);
            fma2(acc2[1][0], aA.y, B0); fma2(acc2[1][1], aA.y, B1);
            fma2(acc2[1][2], aA.y, B2); fma2(acc2[1][3], aA.y, B3);
            fma2(acc2[2][0], aB.x, B0); fma2(acc2[2][1], aB.x, B1);
            fma2(acc2[2][2], aB.x, B2); fma2(acc2[2][3], aB.x, B3);
            fma2(acc2[3][0], aB.y, B0); fma2(acc2[3][1], aB.y, B1);
            fma2(acc2[3][2], aB.y, B2); fma2(acc2[3][3], aB.y, B3);
        }
        __syncthreads();
    }

    // gate: combine the two k-halves (adjacent threads) and write
    gacc += __shfl_xor_sync(0xffffffffu, gacc, 1);
    if ((tid & 1) == 0)
        gate[(size_t)h * E_EDGES + e0 + gr] = gacc + mg_b2[lh];

    // msg output: unpack row pairs
    const float* b2 = mm_b2 + (size_t)lh * F_DIM;
    float4 bias;
    bias.x = b2[tc * 4 + 0]; bias.y = b2[tc * 4 + 1];
    bias.z = b2[tc * 4 + 2]; bias.w = b2[tc * 4 + 3];
#pragma unroll
    for (int rp = 0; rp < 4; rp++) {
        float2 c0 = unpack2(acc2[rp][0]);
        float2 c1 = unpack2(acc2[rp][1]);
        float2 c2 = unpack2(acc2[rp][2]);
        float2 c3 = unpack2(acc2[rp][3]);
        int eLo = e0 + tr * 8 + rp * 2;
        float4 vLo = make_float4(c0.x + bias.x, c1.x + bias.y, c2.x + bias.z, c3.x + bias.w);
        float4 vHi = make_float4(c0.y + bias.x, c1.y + bias.y, c2.y + bias.z, c3.y + bias.w);
        *reinterpret_cast<float4*>(msg + ((size_t)h * E_EDGES + eLo) * F_DIM + tc * 4) = vLo;
        *reinterpret_cast<float4*>(msg + ((size_t)h * E_EDGES + eLo + 1) * F_DIM + tc * 4) = vHi;
    }
}

// ---------------------------------------------------------------------------
// Generic GEMM Y = act(X @ W + b)  (pooling path), packed f32x2
// ---------------------------------------------------------------------------
__global__ __launch_bounds__(256) void gemm_bias_act(
    const float* __restrict__ X, const float* __restrict__ W,
    const float* __restrict__ bias, float* __restrict__ Y,
    int M, int Kd, int N, int doSelu)
{
    __shared__ float As[64][17];
    __shared__ __align__(16) float Bs[16][64];
    const int tid  = threadIdx.x;
    const int row0 = blockIdx.y * 64;
    const int col0 = blockIdx.x * 64;
    const int tr = tid >> 4, tc = tid & 15;

    unsigned long long acc2[4][2];
#pragma unroll
    for (int i = 0; i < 4; i++) { acc2[i][0] = 0ull; acc2[i][1] = 0ull; }

    const int ar = tid >> 2, ac = (tid & 3) << 2;
    const int br = tid >> 4, bc = (tid & 15) << 2;

    for (int k0 = 0; k0 < Kd; k0 += 16) {
        float4 av = *reinterpret_cast<const float4*>(X + (size_t)(row0 + ar) * Kd + k0 + ac);
        As[ar][ac + 0] = av.x; As[ar][ac + 1] = av.y;
        As[ar][ac + 2] = av.z; As[ar][ac + 3] = av.w;
        float4 bv = *reinterpret_cast<const float4*>(W + (size_t)(k0 + br) * N + col0 + bc);
        *reinterpret_cast<float4*>(&Bs[br][bc]) = bv;
        __syncthreads();
#pragma unroll
        for (int k = 0; k < 16; k++) {
            const unsigned long long* bp =
                reinterpret_cast<const unsigned long long*>(&Bs[k][tc * 4]);
            unsigned long long b01 = bp[0], b23 = bp[1];
            unsigned long long A0 = bcast2(As[tr * 4 + 0][k]);
            unsigned long long A1 = bcast2(As[tr * 4 + 1][k]);
            unsigned long long A2 = bcast2(As[tr * 4 + 2][k]);
            unsigned long long A3 = bcast2(As[tr * 4 + 3][k]);
            fma2(acc2[0][0], A0, b01); fma2(acc2[0][1], A0, b23);
            fma2(acc2[1][0], A1, b01); fma2(acc2[1][1], A1, b23);
            fma2(acc2[2][0], A2, b01); fma2(acc2[2][1], A2, b23);
            fma2(acc2[3][0], A3, b01); fma2(acc2[3][1], A3, b23);
        }
        __syncthreads();
    }
#pragma unroll
    for (int i = 0; i < 4; i++) {
        int r = row0 + tr * 4 + i;
        float2 v01 = unpack2(acc2[i][0]);
        float2 v23 = unpack2(acc2[i][1]);
        float vv[4] = {v01.x, v01.y, v23.x, v23.y};
#pragma unroll
        for (int j = 0; j < 4; j++) {
            int c = col0 + tc * 4 + j;
            float v = vv[j] + bias[c];
            if (doSelu) v = selu_f(v);
            Y[(size_t)r * N + c] = v;
        }
    }
}

__global__ __launch_bounds__(256) void rowdot256(
    const float* __restrict__ H, const float* __restrict__ w2,
    const float* __restrict__ b2, float* __restrict__ out)
{
    int row  = blockIdx.x * 8 + (threadIdx.x >> 5);
    int lane = threadIdx.x & 31;
    const float* h = H + (size_t)row * HID_DIM;
    float s = 0.f;
#pragma unroll
    for (int k = lane; k < HID_DIM; k += 32) s += h[k] * w2[k];
#pragma unroll
    for (int o = 16; o; o >>= 1) s += __shfl_xor_sync(0xffffffffu, s, o);
    if (lane == 0) out[row] = s + b2[0];
}

__global__ __launch_bounds__(64) void embed_kernel(
    const float* __restrict__ X, const float* __restrict__ W,
    const float* __restrict__ b, const float* __restrict__ w,
    float* __restrict__ fea)
{
    __shared__ float row[EMB_DIM];
    int n = blockIdx.x, tid = threadIdx.x;
    for (int i = tid; i < EMB_DIM; i += 64) row[i] = X[(size_t)n * EMB_DIM + i];
    __syncthreads();
    if (tid < 63) {
        float s = b[tid];
#pragma unroll 8
        for (int k = 0; k < EMB_DIM; k++) s += row[k] * W[k * 63 + tid];
        fea[n * F_DIM + tid] = s;
    } else {
        fea[n * F_DIM + 63] = w[n];
    }
}

__global__ __launch_bounds__(64) void node_agg(
    const float* __restrict__ gate, const float* __restrict__ msg,
    const float* __restrict__ ew, const int* __restrict__ nbr_idx,
    const float* __restrict__ powp, float* __restrict__ fea)
{
    __shared__ float attn[H_HEADS][DEG];
    int n = blockIdx.x, tid = threadIdx.x;
    if (tid < H_HEADS) {
        int h = tid;
        float pw = powp[h];
        float g[DEG], t[DEG];
        float mx = -1e30f;
#pragma unroll
        for (int e = 0; e < DEG; e++) {
            g[e] = gate[(size_t)h * E_EDGES + n * DEG + e];
            mx = fmaxf(mx, g[e]);
        }
        float den = 0.f;
#pragma unroll
        for (int e = 0; e < DEG; e++) {
            float wv = powf(ew[nbr_idx[n * DEG + e]], pw);
            t[e] = wv * expf(g[e] - mx);
            den += t[e];
        }
        den += 1e-10f;
        float inv = 1.f / den;
#pragma unroll
        for (int e = 0; e < DEG; e++) attn[h][e] = t[e] * inv;
    }
    __syncthreads();
    float acc = 0.f;
#pragma unroll
    for (int h = 0; h < H_HEADS; h++)
#pragma unroll
        for (int e = 0; e < DEG; e++)
            acc += attn[h][e] * msg[((size_t)h * E_EDGES + n * DEG + e) * F_DIM + tid];
    fea[n * F_DIM + tid] += acc * (1.f / 3.f);
}

__global__ __launch_bounds__(64) void graph_agg(
    const float* __restrict__ gate, const float* __restrict__ msg,
    const float* __restrict__ ew, const float* __restrict__ powp,
    float* __restrict__ out)
{
    __shared__ float attn[H_HEADS][K_ATOMS];
    int g = blockIdx.x, tid = threadIdx.x;
    if (tid < H_HEADS) {
        int h = tid;
        float pw = powp[h];
        float gg[K_ATOMS], t[K_ATOMS];
        float mx = -1e30f;
#pragma unroll
        for (int e = 0; e < K_ATOMS; e++) {
            gg[e] = gate[(size_t)h * N_NODES + g * K_ATOMS + e];
            mx = fmaxf(mx, gg[e]);
        }
        float den = 0.f;
#pragma unroll
        for (int e = 0; e < K_ATOMS; e++) {
            float wv = powf(ew[g * K_ATOMS + e], pw);
            t[e] = wv * expf(gg[e] - mx);
            den += t[e];
        }
        den += 1e-10f;
        float inv = 1.f / den;
#pragma unroll
        for (int e = 0; e < K_ATOMS; e++) attn[h][e] = t[e] * inv;
    }
    __syncthreads();
    float acc = 0.f;
#pragma unroll
    for (int h = 0; h < H_HEADS; h++)
#pragma unroll
        for (int e = 0; e < K_ATOMS; e++)
            acc += attn[h][e] * msg[((size_t)h * N_NODES + g * K_ATOMS + e) * F_DIM + tid];
    out[g * F_DIM + tid] = acc * (1.f / 3.f);
}

extern "C" void kernel_launch(void* const* d_in, const int* in_sizes, int n_in,
                              void* d_out, int out_size)
{
    const float* elem_weights = (const float*)d_in[0];
    const float* elem_fea_in  = (const float*)d_in[1];
    const float* W_init       = (const float*)d_in[2];
    const float* b_init       = (const float*)d_in[3];
    const float* mg_W1        = (const float*)d_in[4];
    const float* mg_b1        = (const float*)d_in[5];
    const float* mg_W2        = (const float*)d_in[6];
    const float* mg_b2        = (const float*)d_in[7];
    const float* mm_W1        = (const float*)d_in[8];
    const float* mm_b1        = (const float*)d_in[9];
    const float* mm_W2        = (const float*)d_in[10];
    const float* mm_b2        = (const float*)d_in[11];
    const float* m_pow        = (const float*)d_in[12];
    const float* cg_W1        = (const float*)d_in[13];
    const float* cg_b1        = (const float*)d_in[14];
    const float* cg_W2        = (const float*)d_in[15];
    const float* cg_b2        = (const float*)d_in[16];
    const float* cm_W1        = (const float*)d_in[17];
    const float* cm_b1        = (const float*)d_in[18];
    const float* cm_W2        = (const float*)d_in[19];
    const float* cm_b2        = (const float*)d_in[20];
    const float* c_pow        = (const float*)d_in[21];
    const int*   nbr_idx      = (const int*)d_in[24];

    float *fea, *AB, *hid, *gate, *msg;
    cudaGetSymbolAddress((void**)&fea,  g_fea);
    cudaGetSymbolAddress((void**)&AB,   g_AB);
    cudaGetSymbolAddress((void**)&hid,  g_hid);
    cudaGetSymbolAddress((void**)&gate, g_gate);
    cudaGetSymbolAddress((void**)&msg,  g_msg);

    embed_kernel<<<N_NODES, 64>>>(elem_fea_in, W_init, b_init, elem_weights, fea);

    for (int l = 0; l < L_LAYERS; l++) {
        node_gemm<<<dim3(HID_DIM / 64, N_NODES / 64, 12), 256>>>(fea, mg_W1, mm_W1, AB, l);
        msg_gate_gemm<<<dim3(E_EDGES / 128, 1, H_HEADS), 256>>>(
            AB, mg_b1, mg_W2, mg_b2, mm_b1, mm_W2, mm_b2, nbr_idx, gate, msg, l);
        node_agg<<<N_NODES, 64>>>(gate, msg, elem_weights, nbr_idx,
                                  m_pow + l * H_HEADS, fea);
    }

    for (int h = 0; h < H_HEADS; h++) {
        gemm_bias_act<<<dim3(HID_DIM / 64, N_NODES / 64), 256>>>(
            fea, cg_W1 + (size_t)h * F_DIM * HID_DIM, cg_b1 + (size_t)h * HID_DIM,
            hid, N_NODES, F_DIM, HID_DIM, 1);
        rowdot256<<<N_NODES / 8, 256>>>(hid, cg_W2 + (size_t)h * HID_DIM,
                                        cg_b2 + h, gate + (size_t)h * N_NODES);
        gemm_bias_act<<<dim3(HID_DIM / 64, N_NODES / 64), 256>>>(
            fea, cm_W1 + (size_t)h * F_DIM * HID_DIM, cm_b1 + (size_t)h * HID_DIM,
            hid, N_NODES, F_DIM, HID_DIM, 1);
        gemm_bias_act<<<dim3(F_DIM / 64, N_NODES / 64), 256>>>(
            hid, cm_W2 + (size_t)h * HID_DIM * F_DIM, cm_b2 + (size_t)h * F_DIM,
            msg + (size_t)h * N_NODES * F_DIM, N_NODES, HID_DIM, F_DIM, 0);
    }

    graph_agg<<<G_GRAPHS, 64>>>(gate, msg, elem_weights, c_pow, (float*)d_out);
}

// round 8
// speedup vs baseline: 1.0040x; 1.0008x over previous
#include <cuda_runtime.h>
#include <math.h>

#define G_GRAPHS 256
#define K_ATOMS  16
#define N_NODES  4096
#define E_EDGES  61440
#define DEG      15
#define L_LAYERS 3
#define H_HEADS  3
#define F_DIM    64
#define EMB_DIM  200
#define HID_DIM  256

// Scratch buffers (device globals; no allocation allowed)
__device__ float g_fea [N_NODES * F_DIM];
__device__ float g_AB  [(size_t)12 * N_NODES * HID_DIM];   // [h][net][half][n][256]
__device__ float g_hid [(size_t)N_NODES * HID_DIM];
__device__ float g_gate[(size_t)H_HEADS * E_EDGES];
__device__ float g_msg [(size_t)H_HEADS * E_EDGES * F_DIM];

#define ZOFF(h, net, half) ((size_t)((((h)*2 + (net))*2 + (half))) * N_NODES * HID_DIM)

__device__ __forceinline__ float selu_f(float x) {
    const float scale = 1.0507009873554804934193349852946f;
    const float alpha = 1.6732632423543772848170429916717f;
    return x > 0.f ? scale * x : scale * alpha * (__expf(x) - 1.f);
}

// ---- packed fp32x2 helpers (sm_100+ PTX; ptxas never emits FFMA2 from C++) --
__device__ __forceinline__ unsigned long long bcast2(float x) {
    unsigned long long r;
    asm("mov.b64 %0, {%1, %1};" : "=l"(r) : "f"(x));
    return r;
}
__device__ __forceinline__ void fma2(unsigned long long& d,
                                     unsigned long long a, unsigned long long b) {
    asm("fma.rn.f32x2 %0, %1, %2, %0;" : "+l"(d) : "l"(a), "l"(b));
}
__device__ __forceinline__ float2 unpack2(unsigned long long v) {
    float lo, hi;
    asm("mov.b64 {%0, %1}, %2;" : "=f"(lo), "=f"(hi) : "l"(v));
    return make_float2(lo, hi);
}

// ---------------------------------------------------------------------------
// Batched node projection GEMM for one layer:
// AB[z] = fea[4096,64] @ W_z[64,256]   for z in 0..11  (h, net, half)
// ---------------------------------------------------------------------------
__global__ __launch_bounds__(256) void node_gemm(
    const float* __restrict__ fea, const float* __restrict__ mgW1,
    const float* __restrict__ mmW1, float* __restrict__ AB, int l)
{
    const int z    = blockIdx.z;
    const int h    = z >> 2;
    const int net  = (z >> 1) & 1;
    const int half = z & 1;
    const int lh   = l * H_HEADS + h;
    const float* W = (net ? mmW1 : mgW1) + ((size_t)lh * 128 + half * 64) * HID_DIM;
    float* Y = AB + (size_t)z * N_NODES * HID_DIM;

    __shared__ float As[64][17];
    __shared__ __align__(16) float Bs[16][64];
    const int tid  = threadIdx.x;
    const int row0 = blockIdx.y * 64;
    const int col0 = blockIdx.x * 64;
    const int tr = tid >> 4, tc = tid & 15;

    unsigned long long acc2[4][2];
#pragma unroll
    for (int i = 0; i < 4; i++) { acc2[i][0] = 0ull; acc2[i][1] = 0ull; }

    const int ar = tid >> 2, ac = (tid & 3) << 2;
    const int br = tid >> 4, bc = (tid & 15) << 2;

#pragma unroll
    for (int k0 = 0; k0 < 64; k0 += 16) {
        float4 av = *reinterpret_cast<const float4*>(fea + (size_t)(row0 + ar) * 64 + k0 + ac);
        As[ar][ac + 0] = av.x; As[ar][ac + 1] = av.y;
        As[ar][ac + 2] = av.z; As[ar][ac + 3] = av.w;
        float4 bv = *reinterpret_cast<const float4*>(W + (size_t)(k0 + br) * HID_DIM + col0 + bc);
        *reinterpret_cast<float4*>(&Bs[br][bc]) = bv;
        __syncthreads();
#pragma unroll
        for (int k = 0; k < 16; k++) {
            const unsigned long long* bp =
                reinterpret_cast<const unsigned long long*>(&Bs[k][tc * 4]);
            unsigned long long b01 = bp[0], b23 = bp[1];
            unsigned long long A0 = bcast2(As[tr * 4 + 0][k]);
            unsigned long long A1 = bcast2(As[tr * 4 + 1][k]);
            unsigned long long A2 = bcast2(As[tr * 4 + 2][k]);
            unsigned long long A3 = bcast2(As[tr * 4 + 3][k]);
            fma2(acc2[0][0], A0, b01); fma2(acc2[0][1], A0, b23);
            fma2(acc2[1][0], A1, b01); fma2(acc2[1][1], A1, b23);
            fma2(acc2[2][0], A2, b01); fma2(acc2[2][1], A2, b23);
            fma2(acc2[3][0], A3, b01); fma2(acc2[3][1], A3, b23);
        }
        __syncthreads();
    }
#pragma unroll
    for (int i = 0; i < 4; i++) {
        int r = row0 + tr * 4 + i;
        float2 v01 = unpack2(acc2[i][0]);
        float2 v23 = unpack2(acc2[i][1]);
        float4 v = make_float4(v01.x, v01.y, v23.x, v23.y);
        *reinterpret_cast<float4*>(Y + (size_t)r * HID_DIM + col0 + tc * 4) = v;
    }
}

// ---------------------------------------------------------------------------
// Fused per-edge gate + message kernel (one head per blockIdx.z):
//   gate[h][e] = selu(Ag[s]+Bg[n]+b1g) . w2g + b2g       (register-reduced)
//   msg [h][e] = selu(Am[s]+Bm[n]+b1m) @ W2[256,64] + b2 (smem-tiled GEMM)
// Tile: 128 edges x 64 outputs, K-tile 16.  Packed f32x2 MMA (row-paired).
// ---------------------------------------------------------------------------
__global__ __launch_bounds__(256) void msg_gate_gemm(
    const float* __restrict__ AB,
    const float* __restrict__ mg_b1, const float* __restrict__ mg_W2,
    const float* __restrict__ mg_b2,
    const float* __restrict__ mm_b1, const float* __restrict__ mm_W2,
    const float* __restrict__ mm_b2,
    const int* __restrict__ nbr_idx,
    float* __restrict__ gate, float* __restrict__ msg, int l)
{
    const int h  = blockIdx.z;
    const int lh = l * H_HEADS + h;
    const int e0 = blockIdx.x * 128;
    const int tid = threadIdx.x;

    __shared__ int   sI[128], nI[128];
    __shared__ float b1m[HID_DIM], b1g[HID_DIM], w2g[HID_DIM];
    __shared__ __align__(16) float As[16][136];
    __shared__ __align__(16) float Bs[16][68];

    if (tid < 128) {
        int e = e0 + tid;
        sI[tid] = e / DEG;
        nI[tid] = nbr_idx[e];
    }
    {   // tid 0..255 covers all 256
        b1m[tid] = mm_b1[(size_t)lh * HID_DIM + tid];
        b1g[tid] = mg_b1[(size_t)lh * HID_DIM + tid];
        w2g[tid] = mg_W2[(size_t)lh * HID_DIM + tid];
    }

    const float* Am = AB + ZOFF(h, 1, 0);
    const float* Bm = AB + ZOFF(h, 1, 1);
    const float* Ag = AB + ZOFF(h, 0, 0);
    const float* Bg = AB + ZOFF(h, 0, 1);
    const float* W2 = mm_W2 + (size_t)lh * HID_DIM * F_DIM;
    __syncthreads();

    const int tr = tid >> 4, tc = tid & 15;   // 16x16 thread grid for MMA
    const int gr = tid >> 1;                  // generation edge row (0..127)
    const int gk = (tid & 1) * 8;             // generation k-offset (0 or 8)
    const int wr = tid >> 4;                  // Bs load row
    const int wc = (tid & 15) * 4;            // Bs load col

    const int sRow = sI[gr], nRow = nI[gr];
    const float* amp = Am + (size_t)sRow * HID_DIM + gk;
    const float* bmp = Bm + (size_t)nRow * HID_DIM + gk;
    const float* agp = Ag + (size_t)sRow * HID_DIM + gk;
    const float* bgp = Bg + (size_t)nRow * HID_DIM + gk;

    // acc2[rp][j]: packed pair of edge rows (tr*8+2rp, tr*8+2rp+1), column tc*4+j
    unsigned long long acc2[4][4];
#pragma unroll
    for (int i = 0; i < 4; i++)
#pragma unroll
        for (int j = 0; j < 4; j++) acc2[i][j] = 0ull;
    float gacc = 0.f;

    for (int k0 = 0; k0 < HID_DIM; k0 += 16) {
        // --- generate msg activation tile As[k][edge] ---
        {
            float4 a0 = *reinterpret_cast<const float4*>(amp + k0);
            float4 a1 = *reinterpret_cast<const float4*>(amp + k0 + 4);
            float4 c0 = *reinterpret_cast<const float4*>(bmp + k0);
            float4 c1 = *reinterpret_cast<const float4*>(bmp + k0 + 4);
            const float* bb = b1m + k0 + gk;
            As[gk + 0][gr] = selu_f(a0.x + c0.x + bb[0]);
            As[gk + 1][gr] = selu_f(a0.y + c0.y + bb[1]);
            As[gk + 2][gr] = selu_f(a0.z + c0.z + bb[2]);
            As[gk + 3][gr] = selu_f(a0.w + c0.w + bb[3]);
            As[gk + 4][gr] = selu_f(a1.x + c1.x + bb[4]);
            As[gk + 5][gr] = selu_f(a1.y + c1.y + bb[5]);
            As[gk + 6][gr] = selu_f(a1.z + c1.z + bb[6]);
            As[gk + 7][gr] = selu_f(a1.w + c1.w + bb[7]);
        }
        // --- gate partial (register accumulation, no smem) ---
        {
            float4 a0 = *reinterpret_cast<const float4*>(agp + k0);
            float4 a1 = *reinterpret_cast<const float4*>(agp + k0 + 4);
            float4 c0 = *reinterpret_cast<const float4*>(bgp + k0);
            float4 c1 = *reinterpret_cast<const float4*>(bgp + k0 + 4);
            const float* bb = b1g + k0 + gk;
            const float* ww = w2g + k0 + gk;
            gacc += selu_f(a0.x + c0.x + bb[0]) * ww[0];
            gacc += selu_f(a0.y + c0.y + bb[1]) * ww[1];
            gacc += selu_f(a0.z + c0.z + bb[2]) * ww[2];
            gacc += selu_f(a0.w + c0.w + bb[3]) * ww[3];
            gacc += selu_f(a1.x + c1.x + bb[4]) * ww[4];
            gacc += selu_f(a1.y + c1.y + bb[5]) * ww[5];
            gacc += selu_f(a1.z + c1.z + bb[6]) * ww[6];
            gacc += selu_f(a1.w + c1.w + bb[7]) * ww[7];
        }
        // --- W2 tile ---
        *reinterpret_cast<float4*>(&Bs[wr][wc]) =
            *reinterpret_cast<const float4*>(W2 + (size_t)(k0 + wr) * F_DIM + wc);
        __syncthreads();
#pragma unroll
        for (int k = 0; k < 16; k++) {
            // a: 8 consecutive edges as 4 packed u64 lanes (straight from LDS.128)
            const ulonglong2* ap = reinterpret_cast<const ulonglong2*>(&As[k][tr * 8]);
            ulonglong2 aA = ap[0];   // edges (0,1),(2,3)
            ulonglong2 aB = ap[1];   // edges (4,5),(6,7)
            float4 b = *reinterpret_cast<const float4*>(&Bs[k][tc * 4]);
            unsigned long long B0 = bcast2(b.x), B1 = bcast2(b.y);
            unsigned long long B2 = bcast2(b.z), B3 = bcast2(b.w);
            fma2(acc2[0][0], aA.x, B0); fma2(acc2[0][1], aA.x, B1);
            fma2(acc2[0][2], aA.x, B2); fma2(acc2[0][3], aA.x, B3);
            fma2(acc2[1][0], aA.y, B0); fma2(acc2[1][1], aA.y, B1);
            fma2(acc2[1][2], aA.y, B2); fma2(acc2[1][3], aA.y, B3);
            fma2(acc2[2][0], aB.x, B0); fma2(acc2[2][1], aB.x, B1);
            fma2(acc2[2][2], aB.x, B2); fma2(acc2[2][3], aB.x, B3);
            fma2(acc2[3][0], aB.y, B0); fma2(acc2[3][1], aB.y, B1);
            fma2(acc2[3][2], aB.y, B2); fma2(acc2[3][3], aB.y, B3);
        }
        __syncthreads();
    }

    // gate: combine the two k-halves (adjacent threads) and write
    gacc += __shfl_xor_sync(0xffffffffu, gacc, 1);
    if ((tid & 1) == 0)
        gate[(size_t)h * E_EDGES + e0 + gr] = gacc + mg_b2[lh];

    // msg output: unpack row pairs
    const float* b2 = mm_b2 + (size_t)lh * F_DIM;
    float4 bias;
    bias.x = b2[tc * 4 + 0]; bias.y = b2[tc * 4 + 1];
    bias.z = b2[tc * 4 + 2]; bias.w = b2[tc * 4 + 3];
#pragma unroll
    for (int rp = 0; rp < 4; rp++) {
        float2 c0 = unpack2(acc2[rp][0]);
        float2 c1 = unpack2(acc2[rp][1]);
        float2 c2 = unpack2(acc2[rp][2]);
        float2 c3 = unpack2(acc2[rp][3]);
        int eLo = e0 + tr * 8 + rp * 2;
        float4 vLo = make_float4(c0.x + bias.x, c1.x + bias.y, c2.x + bias.z, c3.x + bias.w);
        float4 vHi = make_float4(c0.y + bias.x, c1.y + bias.y, c2.y + bias.z, c3.y + bias.w);
        *reinterpret_cast<float4*>(msg + ((size_t)h * E_EDGES + eLo) * F_DIM + tc * 4) = vLo;
        *reinterpret_cast<float4*>(msg + ((size_t)h * E_EDGES + eLo + 1) * F_DIM + tc * 4) = vHi;
    }
}

// ---------------------------------------------------------------------------
// Generic GEMM Y = act(X @ W + b)  (pooling path), packed f32x2
// ---------------------------------------------------------------------------
__global__ __launch_bounds__(256) void gemm_bias_act(
    const float* __restrict__ X, const float* __restrict__ W,
    const float* __restrict__ bias, float* __restrict__ Y,
    int M, int Kd, int N, int doSelu)
{
    __shared__ float As[64][17];
    __shared__ __align__(16) float Bs[16][64];
    const int tid  = threadIdx.x;
    const int row0 = blockIdx.y * 64;
    const int col0 = blockIdx.x * 64;
    const int tr = tid >> 4, tc = tid & 15;

    unsigned long long acc2[4][2];
#pragma unroll
    for (int i = 0; i < 4; i++) { acc2[i][0] = 0ull; acc2[i][1] = 0ull; }

    const int ar = tid >> 2, ac = (tid & 3) << 2;
    const int br = tid >> 4, bc = (tid & 15) << 2;

    for (int k0 = 0; k0 < Kd; k0 += 16) {
        float4 av = *reinterpret_cast<const float4*>(X + (size_t)(row0 + ar) * Kd + k0 + ac);
        As[ar][ac + 0] = av.x; As[ar][ac + 1] = av.y;
        As[ar][ac + 2] = av.z; As[ar][ac + 3] = av.w;
        float4 bv = *reinterpret_cast<const float4*>(W + (size_t)(k0 + br) * N + col0 + bc);
        *reinterpret_cast<float4*>(&Bs[br][bc]) = bv;
        __syncthreads();
#pragma unroll
        for (int k = 0; k < 16; k++) {
            const unsigned long long* bp =
                reinterpret_cast<const unsigned long long*>(&Bs[k][tc * 4]);
            unsigned long long b01 = bp[0], b23 = bp[1];
            unsigned long long A0 = bcast2(As[tr * 4 + 0][k]);
            unsigned long long A1 = bcast2(As[tr * 4 + 1][k]);
            unsigned long long A2 = bcast2(As[tr * 4 + 2][k]);
            unsigned long long A3 = bcast2(As[tr * 4 + 3][k]);
            fma2(acc2[0][0], A0, b01); fma2(acc2[0][1], A0, b23);
            fma2(acc2[1][0], A1, b01); fma2(acc2[1][1], A1, b23);
            fma2(acc2[2][0], A2, b01); fma2(acc2[2][1], A2, b23);
            fma2(acc2[3][0], A3, b01); fma2(acc2[3][1], A3, b23);
        }
        __syncthreads();
    }
#pragma unroll
    for (int i = 0; i < 4; i++) {
        int r = row0 + tr * 4 + i;
        float2 v01 = unpack2(acc2[i][0]);
        float2 v23 = unpack2(acc2[i][1]);
        float vv[4] = {v01.x, v01.y, v23.x, v23.y};
#pragma unroll
        for (int j = 0; j < 4; j++) {
            int c = col0 + tc * 4 + j;
            float v = vv[j] + bias[c];
            if (doSelu) v = selu_f(v);
            Y[(size_t)r * N + c] = v;
        }
    }
}

__global__ __launch_bounds__(256) void rowdot256(
    const float* __restrict__ H, const float* __restrict__ w2,
    const float* __restrict__ b2, float* __restrict__ out)
{
    int row  = blockIdx.x * 8 + (threadIdx.x >> 5);
    int lane = threadIdx.x & 31;
    const float* h = H + (size_t)row * HID_DIM;
    float s = 0.f;
#pragma unroll
    for (int k = lane; k < HID_DIM; k += 32) s += h[k] * w2[k];
#pragma unroll
    for (int o = 16; o; o >>= 1) s += __shfl_xor_sync(0xffffffffu, s, o);
    if (lane == 0) out[row] = s + b2[0];
}

__global__ __launch_bounds__(64) void embed_kernel(
    const float* __restrict__ X, const float* __restrict__ W,
    const float* __restrict__ b, const float* __restrict__ w,
    float* __restrict__ fea)
{
    __shared__ float row[EMB_DIM];
    int n = blockIdx.x, tid = threadIdx.x;
    for (int i = tid; i < EMB_DIM; i += 64) row[i] = X[(size_t)n * EMB_DIM + i];
    __syncthreads();
    if (tid < 63) {
        float s = b[tid];
#pragma unroll 8
        for (int k = 0; k < EMB_DIM; k++) s += row[k] * W[k * 63 + tid];
        fea[n * F_DIM + tid] = s;
    } else {
        fea[n * F_DIM + 63] = w[n];
    }
}

__global__ __launch_bounds__(64) void node_agg(
    const float* __restrict__ gate, const float* __restrict__ msg,
    const float* __restrict__ ew, const int* __restrict__ nbr_idx,
    const float* __restrict__ powp, float* __restrict__ fea)
{
    __shared__ float attn[H_HEADS][DEG];
    int n = blockIdx.x, tid = threadIdx.x;
    if (tid < H_HEADS) {
        int h = tid;
        float pw = powp[h];
        float g[DEG], t[DEG];
        float mx = -1e30f;
#pragma unroll
        for (int e = 0; e < DEG; e++) {
            g[e] = gate[(size_t)h * E_EDGES + n * DEG + e];
            mx = fmaxf(mx, g[e]);
        }
        float den = 0.f;
#pragma unroll
        for (int e = 0; e < DEG; e++) {
            float wv = powf(ew[nbr_idx[n * DEG + e]], pw);
            t[e] = wv * expf(g[e] - mx);
            den += t[e];
        }
        den += 1e-10f;
        float inv = 1.f / den;
#pragma unroll
        for (int e = 0; e < DEG; e++) attn[h][e] = t[e] * inv;
    }
    __syncthreads();
    float acc = 0.f;
#pragma unroll
    for (int h = 0; h < H_HEADS; h++)
#pragma unroll
        for (int e = 0; e < DEG; e++)
            acc += attn[h][e] * msg[((size_t)h * E_EDGES + n * DEG + e) * F_DIM + tid];
    fea[n * F_DIM + tid] += acc * (1.f / 3.f);
}

__global__ __launch_bounds__(64) void graph_agg(
    const float* __restrict__ gate, const float* __restrict__ msg,
    const float* __restrict__ ew, const float* __restrict__ powp,
    float* __restrict__ out)
{
    __shared__ float attn[H_HEADS][K_ATOMS];
    int g = blockIdx.x, tid = threadIdx.x;
    if (tid < H_HEADS) {
        int h = tid;
        float pw = powp[h];
        float gg[K_ATOMS], t[K_ATOMS];
        float mx = -1e30f;
#pragma unroll
        for (int e = 0; e < K_ATOMS; e++) {
            gg[e] = gate[(size_t)h * N_NODES + g * K_ATOMS + e];
            mx = fmaxf(mx, gg[e]);
        }
        float den = 0.f;
#pragma unroll
        for (int e = 0; e < K_ATOMS; e++) {
            float wv = powf(ew[g * K_ATOMS + e], pw);
            t[e] = wv * expf(gg[e] - mx);
            den += t[e];
        }
        den += 1e-10f;
        float inv = 1.f / den;
#pragma unroll
        for (int e = 0; e < K_ATOMS; e++) attn[h][e] = t[e] * inv;
    }
    __syncthreads();
    float acc = 0.f;
#pragma unroll
    for (int h = 0; h < H_HEADS; h++)
#pragma unroll
        for (int e = 0; e < K_ATOMS; e++)
            acc += attn[h][e] * msg[((size_t)h * N_NODES + g * K_ATOMS + e) * F_DIM + tid];
    out[g * F_DIM + tid] = acc * (1.f / 3.f);
}

extern "C" void kernel_launch(void* const* d_in, const int* in_sizes, int n_in,
                              void* d_out, int out_size)
{
    const float* elem_weights = (const float*)d_in[0];
    const float* elem_fea_in  = (const float*)d_in[1];
    const float* W_init       = (const float*)d_in[2];
    const float* b_init       = (const float*)d_in[3];
    const float* mg_W1        = (const float*)d_in[4];
    const float* mg_b1        = (const float*)d_in[5];
    const float* mg_W2        = (const float*)d_in[6];
    const float* mg_b2        = (const float*)d_in[7];
    const float* mm_W1        = (const float*)d_in[8];
    const float* mm_b1        = (const float*)d_in[9];
    const float* mm_W2        = (const float*)d_in[10];
    const float* mm_b2        = (const float*)d_in[11];
    const float* m_pow        = (const float*)d_in[12];
    const float* cg_W1        = (const float*)d_in[13];
    const float* cg_b1        = (const float*)d_in[14];
    const float* cg_W2        = (const float*)d_in[15];
    const float* cg_b2        = (const float*)d_in[16];
    const float* cm_W1        = (const float*)d_in[17];
    const float* cm_b1        = (const float*)d_in[18];
    const float* cm_W2        = (const float*)d_in[19];
    const float* cm_b2        = (const float*)d_in[20];
    const float* c_pow        = (const float*)d_in[21];
    const int*   nbr_idx      = (const int*)d_in[24];

    float *fea, *AB, *hid, *gate, *msg;
    cudaGetSymbolAddress((void**)&fea,  g_fea);
    cudaGetSymbolAddress((void**)&AB,   g_AB);
    cudaGetSymbolAddress((void**)&hid,  g_hid);
    cudaGetSymbolAddress((void**)&gate, g_gate);
    cudaGetSymbolAddress((void**)&msg,  g_msg);

    embed_kernel<<<N_NODES, 64>>>(elem_fea_in, W_init, b_init, elem_weights, fea);

    for (int l = 0; l < L_LAYERS; l++) {
        node_gemm<<<dim3(HID_DIM / 64, N_NODES / 64, 12), 256>>>(fea, mg_W1, mm_W1, AB, l);
        msg_gate_gemm<<<dim3(E_EDGES / 128, 1, H_HEADS), 256>>>(
            AB, mg_b1, mg_W2, mg_b2, mm_b1, mm_W2, mm_b2, nbr_idx, gate, msg, l);
        node_agg<<<N_NODES, 64>>>(gate, msg, elem_weights, nbr_idx,
                                  m_pow + l * H_HEADS, fea);
    }

    for (int h = 0; h < H_HEADS; h++) {
        gemm_bias_act<<<dim3(HID_DIM / 64, N_NODES / 64), 256>>>(
            fea, cg_W1 + (size_t)h * F_DIM * HID_DIM, cg_b1 + (size_t)h * HID_DIM,
            hid, N_NODES, F_DIM, HID_DIM, 1);
        rowdot256<<<N_NODES / 8, 256>>>(hid, cg_W2 + (size_t)h * HID_DIM,
                                        cg_b2 + h, gate + (size_t)h * N_NODES);
        gemm_bias_act<<<dim3(HID_DIM / 64, N_NODES / 64), 256>>>(
            fea, cm_W1 + (size_t)h * F_DIM * HID_DIM, cm_b1 + (size_t)h * HID_DIM,
            hid, N_NODES, F_DIM, HID_DIM, 1);
        gemm_bias_act<<<dim3(F_DIM / 64, N_NODES / 64), 256>>>(
            hid, cm_W2 + (size_t)h * HID_DIM * F_DIM, cm_b2 + (size_t)h * F_DIM,
            msg + (size_t)h * N_NODES * F_DIM, N_NODES, HID_DIM, F_DIM, 0);
    }

    graph_agg<<<G_GRAPHS, 64>>>(gate, msg, elem_weights, c_pow, (float*)d_out);
}